// round 4
// baseline (speedup 1.0000x reference)
#include <cuda_runtime.h>

// PositionalEncodingLayer: out[b,t,d] = X[b,t,d] + pe[t,d]
//   pe[t, 2i]   = sin(t / 10000^(2i/d))
//   pe[t, 2i+1] = cos(t / 10000^(2i/d))
// B=8, T=4096, D=1024, fp32.
//
// Round 4 = Round 3 resubmitted (R3 bench was an infra failure: container
// died twice, kernel never ran). Occupancy push: R2 showed regs=52 ->
// 4 blocks/SM -> occ 41% -> DRAM stuck at 68%. Halve live float4 state
// (8 -> 4) with a 2-stage pipeline (second-half loads interleaved with
// first-half stores) and pin occupancy with __launch_bounds__(256, 6)
// -> 6 blocks/SM, 75% theoretical occ.

constexpr int Bn  = 8;
constexpr int Tn  = 4096;
constexpr int Dn  = 1024;
constexpr int C4  = Dn / 4;            // 256 float4 chunks per row
constexpr int PLANE4 = Tn * C4;        // float4 per batch plane (1,048,576)

__global__ __launch_bounds__(C4, 6)
void pe_add_kernel(const float4* __restrict__ X, float4* __restrict__ O)
{
    const int j = threadIdx.x;             // column chunk: cols 4j..4j+3
    const int t = blockIdx.x;              // row
    const int idx = t * C4 + j;            // fits in int32 (max 8M)
    const float4* xin = X + idx;
    float4*       out = O + idx;

    // Stage 1: first 4 batch planes in flight while trig computes.
    float4 v0 = __ldcs(xin + 0 * PLANE4);
    float4 v1 = __ldcs(xin + 1 * PLANE4);
    float4 v2 = __ldcs(xin + 2 * PLANE4);
    float4 v3 = __ldcs(xin + 3 * PLANE4);

    // pe for this thread's 4 columns.
    // inv_freq_i = 10000^(-2i/D) = exp2(-i * 2*log2(10000)/D)
    const float k  = 0.02595256306250292f; // 2*log2(10000)/1024
    const float i0 = (float)(2 * j);
    const float f0 = exp2f(-i0 * k);
    const float f1 = exp2f(-(i0 + 1.0f) * k);
    float s0, c0, s1, c1;
    sincosf((float)t * f0, &s0, &c0);
    sincosf((float)t * f1, &s1, &c1);

    // Stage 2 loads interleaved with stage-1 stores: DRAM latency of batches
    // 4..7 hides under the stores of 0..3; only 4 float4 live at any point.
    v0.x += s0; v0.y += c0; v0.z += s1; v0.w += c1;
    __stcs(out + 0 * PLANE4, v0);
    float4 v4 = __ldcs(xin + 4 * PLANE4);

    v1.x += s0; v1.y += c0; v1.z += s1; v1.w += c1;
    __stcs(out + 1 * PLANE4, v1);
    float4 v5 = __ldcs(xin + 5 * PLANE4);

    v2.x += s0; v2.y += c0; v2.z += s1; v2.w += c1;
    __stcs(out + 2 * PLANE4, v2);
    float4 v6 = __ldcs(xin + 6 * PLANE4);

    v3.x += s0; v3.y += c0; v3.z += s1; v3.w += c1;
    __stcs(out + 3 * PLANE4, v3);
    float4 v7 = __ldcs(xin + 7 * PLANE4);

    v4.x += s0; v4.y += c0; v4.z += s1; v4.w += c1;
    __stcs(out + 4 * PLANE4, v4);
    v5.x += s0; v5.y += c0; v5.z += s1; v5.w += c1;
    __stcs(out + 5 * PLANE4, v5);
    v6.x += s0; v6.y += c0; v6.z += s1; v6.w += c1;
    __stcs(out + 6 * PLANE4, v6);
    v7.x += s0; v7.y += c0; v7.z += s1; v7.w += c1;
    __stcs(out + 7 * PLANE4, v7);
}

extern "C" void kernel_launch(void* const* d_in, const int* in_sizes, int n_in,
                              void* d_out, int out_size)
{
    (void)in_sizes; (void)n_in; (void)out_size;
    const float4* X = (const float4*)d_in[0];
    float4*       O = (float4*)d_out;
    pe_add_kernel<<<Tn, C4>>>(X, O);
}